// round 15
// baseline (speedup 1.0000x reference)
#include <cuda_runtime.h>

#define NN   524288      // nodes
#define NE   12582912    // edges
#define NB   64          // graphs
#define NPER 8192        // nodes per graph
#define F0   8
#define HID  5
#define TILE 2048        // edges per scatter tile (NE = 2048 * 6144 exactly)
#define NTILE 6144
#define TPB  256
#define CAPG 212992      // per-graph record capacity (even; mean 196608, +~37 sigma)
#define NSLICE 7         // edgeB slices per graph -> 448 CTAs ~ 3.03 waves

// ---------------- device scratch (static; no allocation allowed) ----------------
// 8B record: {idx = sl | dl<<13, ea = 4x fp8 e4m3}; 16B-aligned for paired loads
__device__ __align__(16) uint2 g_rec[(size_t)NB * CAPG];  // 109 MB records
__device__ int      g_gcnt[NB * 128];             // per-graph cursors, 512B apart
__device__ float    g_xn[NN * F0];
__device__ float    g_h1[NN * HID];
__device__ float    g_h2[NN * HID];
__device__ float    g_xl[NN * 5];                 // fp32 (node pass / table source)
__device__ float    g_xr[NN * 5];
__device__ uint2    g_x8l[NN];                    // fp8 e4m3 rows (edge-pass tables)
__device__ uint2    g_x8r[NN];
__device__ uint4    g_accb[NN];                   // bf16x2 x4: {d,n0 | n1,n2 | n3,n4 | pad}
__device__ float    g_part[512 * 16];             // gn partials
__device__ float    g_ppart[512 * 18];            // pool partials
__device__ int      g_ticket2;
__device__ double   g_easum[4];
__device__ float4   g_eamean;

// single 128-bit bf16x2 vector reduction (fire-and-forget; 6 live lanes + 2 pad)
__device__ __forceinline__ void red_bf16x8(uint4* p, unsigned w0, unsigned w1,
                                           unsigned w2, unsigned w3) {
    asm volatile("red.global.add.noftz.v4.bf16x2 [%0], {%1,%2,%3,%4};"
                 :: "l"(p), "r"(w0), "r"(w1), "r"(w2), "r"(w3) : "memory");
}

// bf16 helpers
__device__ __forceinline__ unsigned bf16x2pack(float hi, float lo) {
    unsigned r;
    asm("cvt.rn.bf16x2.f32 %0, %1, %2;" : "=r"(r) : "f"(hi), "f"(lo));
    return r;
}
__device__ __forceinline__ float bf_lo(unsigned u) { return __uint_as_float(u << 16); }
__device__ __forceinline__ float bf_hi(unsigned u) { return __uint_as_float(u & 0xFFFF0000u); }

// Schraudolph fast exp: 1 FFMA + 1 F2I, no MUFU. ~4% max rel error (softmax-safe).
__device__ __forceinline__ float fexp(float x) {
    x = fminf(fmaxf(x, -80.f), 80.f);
    int i = __float2int_rn(fmaf(x, 12102203.0f, 1064866805.0f));
    return __int_as_float(i);
}

// fp8 e4m3 helpers
__device__ __forceinline__ unsigned short e4m3x2(float hi, float lo) {
    unsigned short r;
    asm("cvt.rn.satfinite.e4m3x2.f32 %0, %1, %2;" : "=h"(r) : "f"(hi), "f"(lo));
    return r;
}
__device__ __forceinline__ uint2 pack_fp8row(const float* v) {
    uint2 w;
    w.x = (unsigned)e4m3x2(v[1], v[0]) | ((unsigned)e4m3x2(v[3], v[2]) << 16);
    w.y = (unsigned)e4m3x2(0.f, v[4]);
    return w;
}
__device__ __forceinline__ void dec_f16pair(unsigned h, float* a, float* b) {
    asm("{.reg .f16 x,y; mov.b32 {x,y}, %2; cvt.f32.f16 %0,x; cvt.f32.f16 %1,y;}"
        : "=f"(*a), "=f"(*b) : "r"(h));
}
__device__ __forceinline__ void dec_fp8row(uint2 w, float* v) {
    unsigned h01, h23, h4;
    asm("cvt.rn.f16x2.e4m3x2 %0, %1;" : "=r"(h01) : "h"((unsigned short)(w.x & 0xFFFFu)));
    asm("cvt.rn.f16x2.e4m3x2 %0, %1;" : "=r"(h23) : "h"((unsigned short)(w.x >> 16)));
    asm("cvt.rn.f16x2.e4m3x2 %0, %1;" : "=r"(h4)  : "h"((unsigned short)(w.y & 0xFFFFu)));
    float dead;
    dec_f16pair(h01, v + 0, v + 1);
    dec_f16pair(h23, v + 2, v + 3);
    dec_f16pair(h4,  v + 4, &dead);
}
__device__ __forceinline__ unsigned pack_fp8quad(float4 e) {
    return (unsigned)e4m3x2(e.y, e.x) | ((unsigned)e4m3x2(e.w, e.z) << 16);
}
__device__ __forceinline__ void dec_fp8quad(unsigned w, float* v) {
    unsigned h01, h23;
    asm("cvt.rn.f16x2.e4m3x2 %0, %1;" : "=r"(h01) : "h"((unsigned short)(w & 0xFFFFu)));
    asm("cvt.rn.f16x2.e4m3x2 %0, %1;" : "=r"(h23) : "h"((unsigned short)(w >> 16)));
    dec_f16pair(h01, v + 0, v + 1);
    dec_f16pair(h23, v + 2, v + 3);
}

// ---------------- gn phase A: per-(graph, 1/8-slice) stats + state zero ----------------
__global__ __launch_bounds__(256) void k_gnA(const float* __restrict__ x) {
    int bid = blockIdx.x, tid = threadIdx.x;
    int g = bid >> 3, c = bid & 7;

    uint4 z4 = make_uint4(0u, 0u, 0u, 0u);
    for (int i = bid * 256 + tid; i < NN; i += 512 * 256)
        g_accb[i] = z4;
    if (bid == 0) {
        if (tid < NB) g_gcnt[tid * 128] = 0;
        if (tid >= 64 && tid < 68) g_easum[tid - 64] = 0.0;
        if (tid == 68) g_ticket2 = 0;
    }

    float s1[F0], s2[F0];
#pragma unroll
    for (int f = 0; f < F0; f++) { s1[f] = 0.f; s2[f] = 0.f; }
    int rbase = g * NPER + c * 1024;
    for (int r = tid; r < 1024; r += 256) {
        const float* row = x + (size_t)(rbase + r) * F0;
#pragma unroll
        for (int f = 0; f < F0; f++) { float v = row[f]; s1[f] += v; s2[f] += v * v; }
    }
#pragma unroll
    for (int off = 16; off > 0; off >>= 1)
#pragma unroll
        for (int f = 0; f < F0; f++) {
            s1[f] += __shfl_xor_sync(0xffffffffu, s1[f], off);
            s2[f] += __shfl_xor_sync(0xffffffffu, s2[f], off);
        }
    __shared__ float sm[8][2 * F0];
    int wp = tid >> 5, lane = tid & 31;
    if (lane == 0) {
#pragma unroll
        for (int f = 0; f < F0; f++) { sm[wp][f] = s1[f]; sm[wp][F0 + f] = s2[f]; }
    }
    __syncthreads();
    if (tid < 16) {
        float t = 0.f;
        for (int k = 0; k < 8; k++) t += sm[k][tid];
        g_part[bid * 16 + tid] = t;
    }
}

// ---------------- gn phase B: normalize + layer-1 lr + fp8 tables ----------------
__global__ __launch_bounds__(256) void k_gnB(const float* __restrict__ x,
                     const float* __restrict__ w, const float* __restrict__ b,
                     const float* __restrict__ ms,
                     const float* __restrict__ Wl, const float* __restrict__ bl,
                     const float* __restrict__ Wr, const float* __restrict__ br) {
    int bid = blockIdx.x, tid = threadIdx.x;
    int g = bid >> 5;

    __shared__ float sWl[40], sWr[40], sbl[5], sbr[5];
    __shared__ float meanms[F0], scale[F0], bias[F0];
    if (tid < 40) { sWl[tid] = Wl[tid]; sWr[tid] = Wr[tid]; }
    if (tid >= 40 && tid < 45) { sbl[tid - 40] = bl[tid - 40]; sbr[tid - 40] = br[tid - 40]; }
    if (tid >= 48 && tid < 48 + F0) {
        int f = tid - 48;
        float t1 = 0.f, t2 = 0.f;
        for (int c = 0; c < 8; c++) {
            t1 += g_part[(g * 8 + c) * 16 + f];
            t2 += g_part[(g * 8 + c) * 16 + F0 + f];
        }
        float mean = t1 / (float)NPER, ex2 = t2 / (float)NPER, m = ms[f];
        float var = ex2 - 2.f * m * mean * mean + m * m * mean * mean;
        meanms[f] = m * mean;
        scale[f] = w[f] * rsqrtf(var + 1e-5f);
        bias[f] = b[f];
    }
    __syncthreads();

    int n = bid * 256 + tid;
    const float* row = x + (size_t)n * F0;
    float xv[F0];
    float* orow = g_xn + (size_t)n * F0;
#pragma unroll
    for (int f = 0; f < F0; f++) {
        xv[f] = scale[f] * (row[f] - meanms[f]) + bias[f];
        orow[f] = xv[f];
    }
    float l[5], rr[5];
#pragma unroll
    for (int j = 0; j < 5; j++) { l[j] = sbl[j]; rr[j] = sbr[j]; }
#pragma unroll
    for (int i = 0; i < F0; i++)
#pragma unroll
        for (int j = 0; j < 5; j++) {
            l[j] = fmaf(xv[i], sWl[i * 5 + j], l[j]);
            rr[j] = fmaf(xv[i], sWr[i * 5 + j], rr[j]);
        }
#pragma unroll
    for (int j = 0; j < 5; j++) { g_xl[(size_t)n * 5 + j] = l[j]; g_xr[(size_t)n * 5 + j] = rr[j]; }
    g_x8l[n] = pack_fp8row(l);
    g_x8r[n] = pack_fp8row(rr);
}

// ---------------- counting-sort scatter: per-graph contiguous 8B records ----------------
#define SC_SMEM (TILE * 8 + TILE + 3 * 64 * 4)

__global__ __launch_bounds__(TPB, 6) void k_scatter4(const int* __restrict__ src,
                                                     const int* __restrict__ dst,
                                                     const float* __restrict__ ea) {
    extern __shared__ char dsm[];
    uint2*         stage = (uint2*)dsm;
    unsigned char* srun  = (unsigned char*)(dsm + TILE * 8);
    int*           hist  = (int*)(dsm + TILE * 9);
    int*           spref = hist + 64;
    int*           sbase = spref + 64;

    int tid = threadIdx.x, bid = blockIdx.x;
    if (tid < 64) hist[tid] = 0;
    __syncthreads();

    int qbase = bid * (TILE / 4);
    const int4* s4 = (const int4*)src;
    const int4* d4 = (const int4*)dst;
    const float4* e4 = (const float4*)ea;

    int4 sv[2];
    int  rank[8];
#pragma unroll
    for (int q = 0; q < 2; q++) sv[q] = __ldcs(s4 + qbase + q * TPB + tid);
#pragma unroll
    for (int q = 0; q < 2; q++) {
        int4 s = sv[q];
        rank[q * 4 + 0] = atomicAdd(&hist[s.x >> 13], 1);
        rank[q * 4 + 1] = atomicAdd(&hist[s.y >> 13], 1);
        rank[q * 4 + 2] = atomicAdd(&hist[s.z >> 13], 1);
        rank[q * 4 + 3] = atomicAdd(&hist[s.w >> 13], 1);
    }
    __syncthreads();

    if (tid == 0) {
        int run = 0;
        for (int i = 0; i < 64; i++) { spref[i] = run; run += hist[i]; }
    }
    __syncthreads();
    if (tid < 64) sbase[tid] = atomicAdd(&g_gcnt[tid * 128], hist[tid]);

    float a0 = 0.f, a1 = 0.f, a2 = 0.f, a3 = 0.f;
#pragma unroll
    for (int q = 0; q < 2; q++) {
        int4 dv = __ldcs(d4 + qbase + q * TPB + tid);
        int sl[4] = {sv[q].x, sv[q].y, sv[q].z, sv[q].w};
        int dl[4] = {dv.x, dv.y, dv.z, dv.w};
#pragma unroll
        for (int k = 0; k < 4; k++) {
            int e = (qbase + q * TPB + tid) * 4 + k;
            float4 ev = __ldcs(e4 + e);
            a0 += ev.x; a1 += ev.y; a2 += ev.z; a3 += ev.w;
            int s = sl[k], d = dl[k];
            int g = s >> 13;
            int r = spref[g] + rank[q * 4 + k];
            stage[r] = make_uint2((unsigned)(s & 8191) | ((unsigned)(d & 8191) << 13),
                                  pack_fp8quad(ev));
            srun[r] = (unsigned char)g;
        }
    }
    __syncthreads();

    for (int i = tid; i < TILE; i += TPB) {
        int g = srun[i];
        size_t pos = (size_t)g * CAPG + sbase[g] + (i - spref[g]);
        g_rec[pos] = stage[i];
    }

    double d0 = a0, d1 = a1, d2 = a2, d3 = a3;
#pragma unroll
    for (int off = 16; off > 0; off >>= 1) {
        d0 += __shfl_xor_sync(0xffffffffu, d0, off);
        d1 += __shfl_xor_sync(0xffffffffu, d1, off);
        d2 += __shfl_xor_sync(0xffffffffu, d2, off);
        d3 += __shfl_xor_sync(0xffffffffu, d3, off);
    }
    __shared__ double sd[8][4];
    int wp = tid >> 5, lane = tid & 31;
    if (lane == 0) { sd[wp][0] = d0; sd[wp][1] = d1; sd[wp][2] = d2; sd[wp][3] = d3; }
    __syncthreads();
    if (tid < 4) {
        double t = 0.0;
        for (int k = 0; k < 8; k++) t += sd[k][tid];
        atomicAdd(&g_easum[tid], t);
    }
    __syncthreads();
    if (tid == 0) {
        __threadfence();
        int t = atomicAdd(&g_ticket2, 1);
        if (t == (int)gridDim.x - 1) {
            __threadfence();
            double inv = 1.0 / (double)NE;
            double e0 = *((volatile double*)&g_easum[0]);
            double e1 = *((volatile double*)&g_easum[1]);
            double e2 = *((volatile double*)&g_easum[2]);
            double e3 = *((volatile double*)&g_easum[3]);
            g_eamean = make_float4((float)(e0 * inv), (float)(e1 * inv),
                                   (float)(e2 * inv), (float)(e3 * inv));
        }
    }
}

// ---------------- edge sweep: fp8 smem tables, paired LDG.128 records ----------------
__global__ __launch_bounds__(1024, 1) void k_edgeB(const float* __restrict__ We,
                                                   const float* __restrict__ att) {
    extern __shared__ uint2 smem8[];
    uint2* s_l = smem8;           // [8192] fp8 rows
    uint2* s_r = smem8 + NPER;    // [8192]

    int g = blockIdx.x / NSLICE, slice = blockIdx.x % NSLICE;
    int gbase = g * NPER;
    int tid = threadIdx.x;

    for (int r = tid; r < NPER; r += 1024) {
        s_l[r] = g_x8l[gbase + r];
        s_r[r] = g_x8r[gbase + r];
    }

    float we[4][5], av[5];
#pragma unroll
    for (int k = 0; k < 4; k++)
#pragma unroll
        for (int j = 0; j < 5; j++) we[k][j] = __ldg(&We[k * 5 + j]);
#pragma unroll
    for (int j = 0; j < 5; j++) av[j] = __ldg(&att[j]);

    int cnt = min(g_gcnt[g * 128], CAPG);
    int npairs = (cnt + 1) >> 1;
    int lo = (int)((long long)npairs * slice / NSLICE);
    int hi = (int)((long long)npairs * (slice + 1) / NSLICE);
    const uint4* rec4 = (const uint4*)(g_rec + (size_t)g * CAPG);
    uint4* accg = g_accb + gbase;
    __syncthreads();

    for (int p = lo + tid; p < hi; p += 1024) {
        uint4 u = rec4[p];                      // two records; default policy (L2 reuse pass 2)
        // ---- edge A (always valid) ----
        {
            int sl = (int)(u.x & 8191u);
            int dl = (int)((u.x >> 13) & 8191u);
            float ew[4];
            dec_fp8quad(u.y, ew);
            float vv[5], rr[5];
            dec_fp8row(s_l[sl], vv);
            dec_fp8row(s_r[dl], rr);
            float logit = 0.f;
#pragma unroll
            for (int j = 0; j < 5; j++) {
                float tt = vv[j] + rr[j];
                tt = fmaf(ew[0], we[0][j], tt);
                tt = fmaf(ew[1], we[1][j], tt);
                tt = fmaf(ew[2], we[2][j], tt);
                tt = fmaf(ew[3], we[3][j], tt);
                tt = (tt > 0.f) ? tt : 0.2f * tt;
                logit = fmaf(av[j], tt, logit);
            }
            float c = fexp(logit);
            red_bf16x8(accg + dl,
                       bf16x2pack(c * vv[0], c),
                       bf16x2pack(c * vv[2], c * vv[1]),
                       bf16x2pack(c * vv[4], c * vv[3]), 0u);
        }
        // ---- edge B (guard odd tail) ----
        if (2 * p + 1 < cnt) {
            int sl = (int)(u.z & 8191u);
            int dl = (int)((u.z >> 13) & 8191u);
            float ew[4];
            dec_fp8quad(u.w, ew);
            float vv[5], rr[5];
            dec_fp8row(s_l[sl], vv);
            dec_fp8row(s_r[dl], rr);
            float logit = 0.f;
#pragma unroll
            for (int j = 0; j < 5; j++) {
                float tt = vv[j] + rr[j];
                tt = fmaf(ew[0], we[0][j], tt);
                tt = fmaf(ew[1], we[1][j], tt);
                tt = fmaf(ew[2], we[2][j], tt);
                tt = fmaf(ew[3], we[3][j], tt);
                tt = (tt > 0.f) ? tt : 0.2f * tt;
                logit = fmaf(av[j], tt, logit);
            }
            float c = fexp(logit);
            red_bf16x8(accg + dl,
                       bf16x2pack(c * vv[0], c),
                       bf16x2pack(c * vv[2], c * vv[1]),
                       bf16x2pack(c * vv[4], c * vv[3]), 0u);
        }
    }
}

// ---------------- node pass: self-loop + normalize (+ lr2 / fp8 tables / re-zero) ----------------
template<int L>
__global__ void k_node(const float* __restrict__ We, const float* __restrict__ att,
                       const float* __restrict__ bo,
                       const float* __restrict__ Wl2, const float* __restrict__ bl2,
                       const float* __restrict__ Wr2, const float* __restrict__ br2) {
    int n = blockIdx.x * blockDim.x + threadIdx.x;
    if (n >= NN) return;

    float xlv[5], xrv[5];
#pragma unroll
    for (int j = 0; j < 5; j++) { xlv[j] = g_xl[(size_t)n * 5 + j]; xrv[j] = g_xr[(size_t)n * 5 + j]; }

    float4 eav = g_eamean;
    float logit = 0.f;
#pragma unroll
    for (int j = 0; j < 5; j++) {
        float t = xlv[j] + xrv[j];
        t = fmaf(eav.x, __ldg(&We[0 * 5 + j]), t);
        t = fmaf(eav.y, __ldg(&We[1 * 5 + j]), t);
        t = fmaf(eav.z, __ldg(&We[2 * 5 + j]), t);
        t = fmaf(eav.w, __ldg(&We[3 * 5 + j]), t);
        t = (t > 0.f) ? t : 0.2f * t;
        logit = fmaf(__ldg(&att[j]), t, logit);
    }
    float c = fexp(logit);

    uint4 q = g_accb[n];
    float d = bf_lo(q.x) + c;
    float num[5] = {bf_hi(q.x) + c * xlv[0], bf_lo(q.y) + c * xlv[1],
                    bf_hi(q.y) + c * xlv[2], bf_lo(q.z) + c * xlv[3],
                    bf_hi(q.z) + c * xlv[4]};
    float inv = 1.f / d;
    float h[5];
#pragma unroll
    for (int j = 0; j < 5; j++) {
        float t = fmaf(num[j], inv, __ldg(&bo[j]));
        h[j] = (t > 0.f) ? t : 0.f;
    }

    if (L == 1) {
#pragma unroll
        for (int j = 0; j < 5; j++) g_h1[n * 5 + j] = h[j];
        g_accb[n] = make_uint4(0u, 0u, 0u, 0u);

        float xv[13];
#pragma unroll
        for (int j = 0; j < 5; j++) xv[j] = h[j];
#pragma unroll
        for (int f = 0; f < 8; f++) xv[5 + f] = g_xn[n * 8 + f];
        float l[5], r[5];
#pragma unroll
        for (int j = 0; j < 5; j++) { l[j] = __ldg(&bl2[j]); r[j] = __ldg(&br2[j]); }
#pragma unroll
        for (int i = 0; i < 13; i++)
#pragma unroll
            for (int j = 0; j < 5; j++) {
                l[j] = fmaf(xv[i], __ldg(&Wl2[i * 5 + j]), l[j]);
                r[j] = fmaf(xv[i], __ldg(&Wr2[i * 5 + j]), r[j]);
            }
#pragma unroll
        for (int j = 0; j < 5; j++) { g_xl[(size_t)n * 5 + j] = l[j]; g_xr[(size_t)n * 5 + j] = r[j]; }
        g_x8l[n] = pack_fp8row(l);
        g_x8r[n] = pack_fp8row(r);
    } else {
#pragma unroll
        for (int j = 0; j < 5; j++) g_h2[n * 5 + j] = h[j];
    }
}

// ---------------- pool phase A: per-(graph, 1/8-slice) 18-feature partial sums ----------------
__global__ __launch_bounds__(256) void k_poolA() {
    int bid = blockIdx.x, tid = threadIdx.x;
    int g = bid >> 3, c = bid & 7;
    int rbase = g * NPER + c * 1024;

    float acc[18];
#pragma unroll
    for (int f = 0; f < 18; f++) acc[f] = 0.f;
    for (int r = tid; r < 1024; r += 256) {
        int n = rbase + r;
#pragma unroll
        for (int j = 0; j < 5; j++) acc[j] += g_h2[n * 5 + j];
#pragma unroll
        for (int j = 0; j < 5; j++) acc[5 + j] += g_h1[n * 5 + j];
#pragma unroll
        for (int f = 0; f < 8; f++) acc[10 + f] += g_xn[n * 8 + f];
    }
#pragma unroll
    for (int off = 16; off > 0; off >>= 1)
#pragma unroll
        for (int f = 0; f < 18; f++) acc[f] += __shfl_xor_sync(0xffffffffu, acc[f], off);
    __shared__ float sm[8][18];
    int wp = tid >> 5, lane = tid & 31;
    if (lane == 0) {
#pragma unroll
        for (int f = 0; f < 18; f++) sm[wp][f] = acc[f];
    }
    __syncthreads();
    if (tid < 18) {
        float t = 0.f;
        for (int k = 0; k < 8; k++) t += sm[k][tid];
        g_ppart[bid * 18 + tid] = t;
    }
}

// ---------------- pool phase B: finish pool + dueling head (64 threads) ----------------
__global__ void k_poolB(const int* __restrict__ cur, const int* __restrict__ mask,
                        const float* __restrict__ goal,
                        const float* __restrict__ Wv1, const float* __restrict__ bv1,
                        const float* __restrict__ Wv2, const float* __restrict__ bv2,
                        const float* __restrict__ Wa1, const float* __restrict__ ba1,
                        const float* __restrict__ Wa2, const float* __restrict__ ba2,
                        float* __restrict__ out) {
    int b = threadIdx.x;
    if (b >= NB) return;
    int n = b * NPER + cur[b];
    float feat[42];
#pragma unroll
    for (int j = 0; j < 5; j++) feat[j] = g_h2[n * 5 + j];
#pragma unroll
    for (int j = 0; j < 5; j++) feat[5 + j] = g_h1[n * 5 + j];
#pragma unroll
    for (int f = 0; f < 8; f++) feat[10 + f] = g_xn[n * 8 + f];
#pragma unroll
    for (int k = 0; k < 18; k++) {
        float t = 0.f;
        for (int c = 0; c < 8; c++) t += g_ppart[(b * 8 + c) * 18 + k];
        feat[18 + k] = t * (1.f / (float)NPER);
    }
#pragma unroll
    for (int k = 0; k < 6; k++) feat[36 + k] = goal[b * 6 + k];

    float hv[10], ha[10];
#pragma unroll
    for (int j = 0; j < 10; j++) { hv[j] = bv1[j]; ha[j] = ba1[j]; }
    for (int i = 0; i < 42; i++) {
        float fi = feat[i];
#pragma unroll
        for (int j = 0; j < 10; j++) {
            hv[j] = fmaf(fi, Wv1[i * 10 + j], hv[j]);
            ha[j] = fmaf(fi, Wa1[i * 10 + j], ha[j]);
        }
    }
#pragma unroll
    for (int j = 0; j < 10; j++) {
        hv[j] = (hv[j] > 0.f) ? hv[j] : 0.f;
        ha[j] = (ha[j] > 0.f) ? ha[j] : 0.f;
    }
    float val = bv2[0];
#pragma unroll
    for (int j = 0; j < 10; j++) val = fmaf(hv[j], Wv2[j], val);
    float adv[4];
#pragma unroll
    for (int k = 0; k < 4; k++) {
        adv[k] = ba2[k];
#pragma unroll
        for (int j = 0; j < 10; j++) adv[k] = fmaf(ha[j], Wa2[j * 4 + k], adv[k]);
    }
    float am = (adv[0] + adv[1] + adv[2] + adv[3]) * 0.25f;
#pragma unroll
    for (int k = 0; k < 4; k++)
        out[b * 4 + k] = (mask[b * 4 + k] == 0) ? -1e8f : (val + adv[k] - am);
}

// ---------------- launch ----------------
extern "C" void kernel_launch(void* const* d_in, const int* in_sizes, int n_in,
                              void* d_out, int out_size) {
    const float* x    = (const float*)d_in[0];
    const int*   ei   = (const int*)d_in[1];
    const float* ea   = (const float*)d_in[2];
    const int*   cur  = (const int*)d_in[4];
    const int*   mask = (const int*)d_in[5];
    const float* goal = (const float*)d_in[6];
    const float* gnw  = (const float*)d_in[7];
    const float* gnb  = (const float*)d_in[8];
    const float* gnms = (const float*)d_in[9];
    const float* Wl1 = (const float*)d_in[10], *bl1 = (const float*)d_in[11];
    const float* Wr1 = (const float*)d_in[12], *br1 = (const float*)d_in[13];
    const float* We1 = (const float*)d_in[14], *att1 = (const float*)d_in[15], *bo1 = (const float*)d_in[16];
    const float* Wl2 = (const float*)d_in[17], *bl2 = (const float*)d_in[18];
    const float* Wr2 = (const float*)d_in[19], *br2 = (const float*)d_in[20];
    const float* We2 = (const float*)d_in[21], *att2 = (const float*)d_in[22], *bo2 = (const float*)d_in[23];
    const float* Wv1 = (const float*)d_in[24], *bv1 = (const float*)d_in[25];
    const float* Wv2 = (const float*)d_in[26], *bv2 = (const float*)d_in[27];
    const float* Wa1 = (const float*)d_in[28], *ba1 = (const float*)d_in[29];
    const float* Wa2 = (const float*)d_in[30], *ba2 = (const float*)d_in[31];

    const int* srcp = ei;
    const int* dstp = ei + NE;

    const int EDGE_SMEM = NPER * 8 * 2;   // 128 KB fp8 tables
    cudaFuncSetAttribute(k_edgeB, cudaFuncAttributeMaxDynamicSharedMemorySize, EDGE_SMEM);
    cudaFuncSetAttribute(k_scatter4, cudaFuncAttributeMaxDynamicSharedMemorySize, SC_SMEM);

    k_gnA<<<512, 256>>>(x);                                             // 1
    k_gnB<<<2048, 256>>>(x, gnw, gnb, gnms, Wl1, bl1, Wr1, br1);        // 2
    k_scatter4<<<NTILE, TPB, SC_SMEM>>>(srcp, dstp, ea);                // 3
    k_edgeB<<<NB * NSLICE, 1024, EDGE_SMEM>>>(We1, att1);               // 4 <- ncu slot
    k_node<1><<<NN / 256, 256>>>(We1, att1, bo1, Wl2, bl2, Wr2, br2);  // 5
    k_edgeB<<<NB * NSLICE, 1024, EDGE_SMEM>>>(We2, att2);               // 6
    k_node<2><<<NN / 256, 256>>>(We2, att2, bo2, 0, 0, 0, 0);          // 7
    k_poolA<<<512, 256>>>();                                            // 8
    k_poolB<<<1, 64>>>(cur, mask, goal, Wv1, bv1, Wv2, bv2,
                       Wa1, ba1, Wa2, ba2, (float*)d_out);              // 9
}

// round 16
// speedup vs baseline: 1.0166x; 1.0166x over previous
#include <cuda_runtime.h>

#define NN   524288      // nodes
#define NE   12582912    // edges
#define NB   64          // graphs
#define NPER 8192        // nodes per graph
#define F0   8
#define HID  5
#define TILE 2048        // edges per scatter tile (NE = 2048 * 6144 exactly)
#define NTILE 6144
#define TPB  256
#define CAPG 212992      // per-graph record capacity (mean 196608, +~37 sigma)
#define NSLICE 7         // edgeB slices per graph -> 448 CTAs ~ 3.03 waves

// ---------------- device scratch (static; no allocation allowed) ----------------
// 8B record: {idx = sl | dl<<13, ea = 4x fp8 e4m3}
__device__ uint2    g_rec[(size_t)NB * CAPG];     // 109 MB per-graph contiguous records
__device__ int      g_gcnt[NB * 128];             // per-graph cursors, 512B apart
__device__ float    g_xn[NN * F0];
__device__ float    g_h1[NN * HID];
__device__ float    g_h2[NN * HID];
__device__ float    g_xl[NN * 5];                 // fp32 (node pass / table source)
__device__ float    g_xr[NN * 5];
__device__ uint2    g_x8l[NN];                    // fp8 e4m3 rows (edge-pass tables)
__device__ uint2    g_x8r[NN];
__device__ uint4    g_accb[NN];                   // bf16x2 x4: {d,n0 | n1,n2 | n3,n4 | pad}
__device__ float    g_part[512 * 16];             // gn partials
__device__ float    g_ppart[512 * 18];            // pool partials
__device__ int      g_ticket2;
__device__ double   g_easum[4];
__device__ float4   g_eamean;

// single 128-bit bf16x2 vector reduction (fire-and-forget; 6 live lanes + 2 pad)
__device__ __forceinline__ void red_bf16x8(uint4* p, unsigned w0, unsigned w1,
                                           unsigned w2, unsigned w3) {
    asm volatile("red.global.add.noftz.v4.bf16x2 [%0], {%1,%2,%3,%4};"
                 :: "l"(p), "r"(w0), "r"(w1), "r"(w2), "r"(w3) : "memory");
}

// bf16 helpers
__device__ __forceinline__ unsigned bf16x2pack(float hi, float lo) {
    unsigned r;
    asm("cvt.rn.bf16x2.f32 %0, %1, %2;" : "=r"(r) : "f"(hi), "f"(lo));
    return r;
}
__device__ __forceinline__ float bf_lo(unsigned u) { return __uint_as_float(u << 16); }
__device__ __forceinline__ float bf_hi(unsigned u) { return __uint_as_float(u & 0xFFFF0000u); }

// Schraudolph fast exp: 1 FFMA + 1 F2I, no MUFU. ~4% max rel error (softmax-safe).
__device__ __forceinline__ float fexp(float x) {
    x = fminf(fmaxf(x, -80.f), 80.f);
    int i = __float2int_rn(fmaf(x, 12102203.0f, 1064866805.0f));
    return __int_as_float(i);
}

// fp8 e4m3 helpers
__device__ __forceinline__ unsigned short e4m3x2(float hi, float lo) {
    unsigned short r;
    asm("cvt.rn.satfinite.e4m3x2.f32 %0, %1, %2;" : "=h"(r) : "f"(hi), "f"(lo));
    return r;
}
__device__ __forceinline__ uint2 pack_fp8row(const float* v) {
    uint2 w;
    w.x = (unsigned)e4m3x2(v[1], v[0]) | ((unsigned)e4m3x2(v[3], v[2]) << 16);
    w.y = (unsigned)e4m3x2(0.f, v[4]);
    return w;
}
__device__ __forceinline__ void dec_f16pair(unsigned h, float* a, float* b) {
    asm("{.reg .f16 x,y; mov.b32 {x,y}, %2; cvt.f32.f16 %0,x; cvt.f32.f16 %1,y;}"
        : "=f"(*a), "=f"(*b) : "r"(h));
}
__device__ __forceinline__ void dec_fp8row(uint2 w, float* v) {
    unsigned h01, h23, h4;
    asm("cvt.rn.f16x2.e4m3x2 %0, %1;" : "=r"(h01) : "h"((unsigned short)(w.x & 0xFFFFu)));
    asm("cvt.rn.f16x2.e4m3x2 %0, %1;" : "=r"(h23) : "h"((unsigned short)(w.x >> 16)));
    asm("cvt.rn.f16x2.e4m3x2 %0, %1;" : "=r"(h4)  : "h"((unsigned short)(w.y & 0xFFFFu)));
    float dead;
    dec_f16pair(h01, v + 0, v + 1);
    dec_f16pair(h23, v + 2, v + 3);
    dec_f16pair(h4,  v + 4, &dead);
}
__device__ __forceinline__ unsigned pack_fp8quad(float4 e) {
    return (unsigned)e4m3x2(e.y, e.x) | ((unsigned)e4m3x2(e.w, e.z) << 16);
}
__device__ __forceinline__ void dec_fp8quad(unsigned w, float* v) {
    unsigned h01, h23;
    asm("cvt.rn.f16x2.e4m3x2 %0, %1;" : "=r"(h01) : "h"((unsigned short)(w & 0xFFFFu)));
    asm("cvt.rn.f16x2.e4m3x2 %0, %1;" : "=r"(h23) : "h"((unsigned short)(w >> 16)));
    dec_f16pair(h01, v + 0, v + 1);
    dec_f16pair(h23, v + 2, v + 3);
}

// shared node-update math: accumulator + self-loop -> h[5]
__device__ __forceinline__ void node_update(int n, const float* __restrict__ We,
                                            const float* __restrict__ att,
                                            const float* __restrict__ bo,
                                            float4 eav, float* xlv, float* xrv, float* h) {
#pragma unroll
    for (int j = 0; j < 5; j++) { xlv[j] = g_xl[(size_t)n * 5 + j]; xrv[j] = g_xr[(size_t)n * 5 + j]; }
    float logit = 0.f;
#pragma unroll
    for (int j = 0; j < 5; j++) {
        float t = xlv[j] + xrv[j];
        t = fmaf(eav.x, __ldg(&We[0 * 5 + j]), t);
        t = fmaf(eav.y, __ldg(&We[1 * 5 + j]), t);
        t = fmaf(eav.z, __ldg(&We[2 * 5 + j]), t);
        t = fmaf(eav.w, __ldg(&We[3 * 5 + j]), t);
        t = (t > 0.f) ? t : 0.2f * t;
        logit = fmaf(__ldg(&att[j]), t, logit);
    }
    float c = fexp(logit);
    uint4 q = g_accb[n];
    float d = bf_lo(q.x) + c;
    float num[5] = {bf_hi(q.x) + c * xlv[0], bf_lo(q.y) + c * xlv[1],
                    bf_hi(q.y) + c * xlv[2], bf_lo(q.z) + c * xlv[3],
                    bf_hi(q.z) + c * xlv[4]};
    float inv = 1.f / d;
#pragma unroll
    for (int j = 0; j < 5; j++) {
        float t = fmaf(num[j], inv, __ldg(&bo[j]));
        h[j] = (t > 0.f) ? t : 0.f;
    }
}

// ---------------- gn phase A: per-(graph, 1/8-slice) stats + state zero ----------------
__global__ __launch_bounds__(256) void k_gnA(const float* __restrict__ x) {
    int bid = blockIdx.x, tid = threadIdx.x;
    int g = bid >> 3, c = bid & 7;

    uint4 z4 = make_uint4(0u, 0u, 0u, 0u);
    for (int i = bid * 256 + tid; i < NN; i += 512 * 256)
        g_accb[i] = z4;
    if (bid == 0) {
        if (tid < NB) g_gcnt[tid * 128] = 0;
        if (tid >= 64 && tid < 68) g_easum[tid - 64] = 0.0;
        if (tid == 68) g_ticket2 = 0;
    }

    float s1[F0], s2[F0];
#pragma unroll
    for (int f = 0; f < F0; f++) { s1[f] = 0.f; s2[f] = 0.f; }
    int rbase = g * NPER + c * 1024;
    for (int r = tid; r < 1024; r += 256) {
        const float* row = x + (size_t)(rbase + r) * F0;
#pragma unroll
        for (int f = 0; f < F0; f++) { float v = row[f]; s1[f] += v; s2[f] += v * v; }
    }
#pragma unroll
    for (int off = 16; off > 0; off >>= 1)
#pragma unroll
        for (int f = 0; f < F0; f++) {
            s1[f] += __shfl_xor_sync(0xffffffffu, s1[f], off);
            s2[f] += __shfl_xor_sync(0xffffffffu, s2[f], off);
        }
    __shared__ float sm[8][2 * F0];
    int wp = tid >> 5, lane = tid & 31;
    if (lane == 0) {
#pragma unroll
        for (int f = 0; f < F0; f++) { sm[wp][f] = s1[f]; sm[wp][F0 + f] = s2[f]; }
    }
    __syncthreads();
    if (tid < 16) {
        float t = 0.f;
        for (int k = 0; k < 8; k++) t += sm[k][tid];
        g_part[bid * 16 + tid] = t;
    }
}

// ---------------- gn phase B: normalize + layer-1 lr + fp8 tables ----------------
__global__ __launch_bounds__(256) void k_gnB(const float* __restrict__ x,
                     const float* __restrict__ w, const float* __restrict__ b,
                     const float* __restrict__ ms,
                     const float* __restrict__ Wl, const float* __restrict__ bl,
                     const float* __restrict__ Wr, const float* __restrict__ br) {
    int bid = blockIdx.x, tid = threadIdx.x;
    int g = bid >> 5;

    __shared__ float sWl[40], sWr[40], sbl[5], sbr[5];
    __shared__ float meanms[F0], scale[F0], bias[F0];
    if (tid < 40) { sWl[tid] = Wl[tid]; sWr[tid] = Wr[tid]; }
    if (tid >= 40 && tid < 45) { sbl[tid - 40] = bl[tid - 40]; sbr[tid - 40] = br[tid - 40]; }
    if (tid >= 48 && tid < 48 + F0) {
        int f = tid - 48;
        float t1 = 0.f, t2 = 0.f;
        for (int c = 0; c < 8; c++) {
            t1 += g_part[(g * 8 + c) * 16 + f];
            t2 += g_part[(g * 8 + c) * 16 + F0 + f];
        }
        float mean = t1 / (float)NPER, ex2 = t2 / (float)NPER, m = ms[f];
        float var = ex2 - 2.f * m * mean * mean + m * m * mean * mean;
        meanms[f] = m * mean;
        scale[f] = w[f] * rsqrtf(var + 1e-5f);
        bias[f] = b[f];
    }
    __syncthreads();

    int n = bid * 256 + tid;
    const float* row = x + (size_t)n * F0;
    float xv[F0];
    float* orow = g_xn + (size_t)n * F0;
#pragma unroll
    for (int f = 0; f < F0; f++) {
        xv[f] = scale[f] * (row[f] - meanms[f]) + bias[f];
        orow[f] = xv[f];
    }
    float l[5], rr[5];
#pragma unroll
    for (int j = 0; j < 5; j++) { l[j] = sbl[j]; rr[j] = sbr[j]; }
#pragma unroll
    for (int i = 0; i < F0; i++)
#pragma unroll
        for (int j = 0; j < 5; j++) {
            l[j] = fmaf(xv[i], sWl[i * 5 + j], l[j]);
            rr[j] = fmaf(xv[i], sWr[i * 5 + j], rr[j]);
        }
#pragma unroll
    for (int j = 0; j < 5; j++) { g_xl[(size_t)n * 5 + j] = l[j]; g_xr[(size_t)n * 5 + j] = rr[j]; }
    g_x8l[n] = pack_fp8row(l);
    g_x8r[n] = pack_fp8row(rr);
}

// ---------------- counting-sort scatter: per-graph contiguous 8B records ----------------
#define SC_SMEM (TILE * 8 + TILE + 3 * 64 * 4)

__global__ __launch_bounds__(TPB, 6) void k_scatter4(const int* __restrict__ src,
                                                     const int* __restrict__ dst,
                                                     const float* __restrict__ ea) {
    extern __shared__ char dsm[];
    uint2*         stage = (uint2*)dsm;
    unsigned char* srun  = (unsigned char*)(dsm + TILE * 8);
    int*           hist  = (int*)(dsm + TILE * 9);
    int*           spref = hist + 64;
    int*           sbase = spref + 64;

    int tid = threadIdx.x, bid = blockIdx.x;
    if (tid < 64) hist[tid] = 0;
    __syncthreads();

    int qbase = bid * (TILE / 4);
    const int4* s4 = (const int4*)src;
    const int4* d4 = (const int4*)dst;
    const float4* e4 = (const float4*)ea;

    int4 sv[2];
    int  rank[8];
#pragma unroll
    for (int q = 0; q < 2; q++) sv[q] = __ldcs(s4 + qbase + q * TPB + tid);
#pragma unroll
    for (int q = 0; q < 2; q++) {
        int4 s = sv[q];
        rank[q * 4 + 0] = atomicAdd(&hist[s.x >> 13], 1);
        rank[q * 4 + 1] = atomicAdd(&hist[s.y >> 13], 1);
        rank[q * 4 + 2] = atomicAdd(&hist[s.z >> 13], 1);
        rank[q * 4 + 3] = atomicAdd(&hist[s.w >> 13], 1);
    }
    __syncthreads();

    if (tid == 0) {
        int run = 0;
        for (int i = 0; i < 64; i++) { spref[i] = run; run += hist[i]; }
    }
    __syncthreads();
    if (tid < 64) sbase[tid] = atomicAdd(&g_gcnt[tid * 128], hist[tid]);

    float a0 = 0.f, a1 = 0.f, a2 = 0.f, a3 = 0.f;
#pragma unroll
    for (int q = 0; q < 2; q++) {
        int4 dv = __ldcs(d4 + qbase + q * TPB + tid);
        int sl[4] = {sv[q].x, sv[q].y, sv[q].z, sv[q].w};
        int dl[4] = {dv.x, dv.y, dv.z, dv.w};
#pragma unroll
        for (int k = 0; k < 4; k++) {
            int e = (qbase + q * TPB + tid) * 4 + k;
            float4 ev = __ldcs(e4 + e);
            a0 += ev.x; a1 += ev.y; a2 += ev.z; a3 += ev.w;
            int s = sl[k], d = dl[k];
            int g = s >> 13;
            int r = spref[g] + rank[q * 4 + k];
            stage[r] = make_uint2((unsigned)(s & 8191) | ((unsigned)(d & 8191) << 13),
                                  pack_fp8quad(ev));
            srun[r] = (unsigned char)g;
        }
    }
    __syncthreads();

    for (int i = tid; i < TILE; i += TPB) {
        int g = srun[i];
        size_t pos = (size_t)g * CAPG + sbase[g] + (i - spref[g]);
        g_rec[pos] = stage[i];
    }

    double d0 = a0, d1 = a1, d2 = a2, d3 = a3;
#pragma unroll
    for (int off = 16; off > 0; off >>= 1) {
        d0 += __shfl_xor_sync(0xffffffffu, d0, off);
        d1 += __shfl_xor_sync(0xffffffffu, d1, off);
        d2 += __shfl_xor_sync(0xffffffffu, d2, off);
        d3 += __shfl_xor_sync(0xffffffffu, d3, off);
    }
    __shared__ double sd[8][4];
    int wp = tid >> 5, lane = tid & 31;
    if (lane == 0) { sd[wp][0] = d0; sd[wp][1] = d1; sd[wp][2] = d2; sd[wp][3] = d3; }
    __syncthreads();
    if (tid < 4) {
        double t = 0.0;
        for (int k = 0; k < 8; k++) t += sd[k][tid];
        atomicAdd(&g_easum[tid], t);
    }
    __syncthreads();
    if (tid == 0) {
        __threadfence();
        int t = atomicAdd(&g_ticket2, 1);
        if (t == (int)gridDim.x - 1) {
            __threadfence();
            double inv = 1.0 / (double)NE;
            double e0 = *((volatile double*)&g_easum[0]);
            double e1 = *((volatile double*)&g_easum[1]);
            double e2 = *((volatile double*)&g_easum[2]);
            double e3 = *((volatile double*)&g_easum[3]);
            g_eamean = make_float4((float)(e0 * inv), (float)(e1 * inv),
                                   (float)(e2 * inv), (float)(e3 * inv));
        }
    }
}

// ---------------- edge sweep: fp8 smem tables, fast-exp, single bf16x8 red ----------------
__global__ __launch_bounds__(1024, 1) void k_edgeB(const float* __restrict__ We,
                                                   const float* __restrict__ att) {
    extern __shared__ uint2 smem8[];
    uint2* s_l = smem8;           // [8192] fp8 rows
    uint2* s_r = smem8 + NPER;    // [8192]

    int g = blockIdx.x / NSLICE, slice = blockIdx.x % NSLICE;
    int gbase = g * NPER;
    int tid = threadIdx.x;

    for (int r = tid; r < NPER; r += 1024) {
        s_l[r] = g_x8l[gbase + r];
        s_r[r] = g_x8r[gbase + r];
    }

    float we[4][5], av[5];
#pragma unroll
    for (int k = 0; k < 4; k++)
#pragma unroll
        for (int j = 0; j < 5; j++) we[k][j] = __ldg(&We[k * 5 + j]);
#pragma unroll
    for (int j = 0; j < 5; j++) av[j] = __ldg(&att[j]);

    int cnt = min(g_gcnt[g * 128], CAPG);
    int lo = (int)((long long)cnt * slice / NSLICE);
    int hi = (int)((long long)cnt * (slice + 1) / NSLICE);
    const uint2* rec = g_rec + (size_t)g * CAPG;
    uint4* accg = g_accb + gbase;
    __syncthreads();

    for (int i = lo + tid; i < hi; i += 1024) {
        uint2 u = __ldcs(rec + i);
        int sl = (int)(u.x & 8191u);
        int dl = (int)((u.x >> 13) & 8191u);
        float ew[4];
        dec_fp8quad(u.y, ew);
        float vv[5], rr[5];
        dec_fp8row(s_l[sl], vv);
        dec_fp8row(s_r[dl], rr);
        float logit = 0.f;
#pragma unroll
        for (int j = 0; j < 5; j++) {
            float tt = vv[j] + rr[j];
            tt = fmaf(ew[0], we[0][j], tt);
            tt = fmaf(ew[1], we[1][j], tt);
            tt = fmaf(ew[2], we[2][j], tt);
            tt = fmaf(ew[3], we[3][j], tt);
            tt = (tt > 0.f) ? tt : 0.2f * tt;
            logit = fmaf(av[j], tt, logit);
        }
        float c = fexp(logit);
        red_bf16x8(accg + dl,
                   bf16x2pack(c * vv[0], c),
                   bf16x2pack(c * vv[2], c * vv[1]),
                   bf16x2pack(c * vv[4], c * vv[3]), 0u);
    }
}

// ---------------- node pass 1: h1 + lr2 + fp8 tables + acc re-zero ----------------
__global__ void k_node1(const float* __restrict__ We, const float* __restrict__ att,
                        const float* __restrict__ bo,
                        const float* __restrict__ Wl2, const float* __restrict__ bl2,
                        const float* __restrict__ Wr2, const float* __restrict__ br2) {
    int n = blockIdx.x * blockDim.x + threadIdx.x;
    if (n >= NN) return;

    float xlv[5], xrv[5], h[5];
    node_update(n, We, att, bo, g_eamean, xlv, xrv, h);

#pragma unroll
    for (int j = 0; j < 5; j++) g_h1[n * 5 + j] = h[j];
    g_accb[n] = make_uint4(0u, 0u, 0u, 0u);

    float xv[13];
#pragma unroll
    for (int j = 0; j < 5; j++) xv[j] = h[j];
#pragma unroll
    for (int f = 0; f < 8; f++) xv[5 + f] = g_xn[n * 8 + f];
    float l[5], r[5];
#pragma unroll
    for (int j = 0; j < 5; j++) { l[j] = __ldg(&bl2[j]); r[j] = __ldg(&br2[j]); }
#pragma unroll
    for (int i = 0; i < 13; i++)
#pragma unroll
        for (int j = 0; j < 5; j++) {
            l[j] = fmaf(xv[i], __ldg(&Wl2[i * 5 + j]), l[j]);
            r[j] = fmaf(xv[i], __ldg(&Wr2[i * 5 + j]), r[j]);
        }
#pragma unroll
    for (int j = 0; j < 5; j++) { g_xl[(size_t)n * 5 + j] = l[j]; g_xr[(size_t)n * 5 + j] = r[j]; }
    g_x8l[n] = pack_fp8row(l);
    g_x8r[n] = pack_fp8row(r);
}

// ---------------- fused node-2 + pool phase A ----------------
// 512 CTAs: (graph, 1/8-slice). Each thread owns 4 consecutive nodes: computes
// h2 inline from accb, writes h2, accumulates the 18 pool sums in registers.
__global__ __launch_bounds__(256) void k_node2poolA(const float* __restrict__ We,
                                                    const float* __restrict__ att,
                                                    const float* __restrict__ bo) {
    int bid = blockIdx.x, tid = threadIdx.x;
    int g = bid >> 3, c = bid & 7;
    int rbase = g * NPER + c * 1024;
    float4 eav = g_eamean;

    float acc[18];
#pragma unroll
    for (int f = 0; f < 18; f++) acc[f] = 0.f;

#pragma unroll
    for (int q = 0; q < 4; q++) {
        int n = rbase + q * 256 + tid;
        float xlv[5], xrv[5], h[5];
        node_update(n, We, att, bo, eav, xlv, xrv, h);
#pragma unroll
        for (int j = 0; j < 5; j++) {
            g_h2[n * 5 + j] = h[j];
            acc[j] += h[j];
            acc[5 + j] += g_h1[n * 5 + j];
        }
#pragma unroll
        for (int f = 0; f < 8; f++) acc[10 + f] += g_xn[n * 8 + f];
    }

#pragma unroll
    for (int off = 16; off > 0; off >>= 1)
#pragma unroll
        for (int f = 0; f < 18; f++) acc[f] += __shfl_xor_sync(0xffffffffu, acc[f], off);
    __shared__ float sm[8][18];
    int wp = tid >> 5, lane = tid & 31;
    if (lane == 0) {
#pragma unroll
        for (int f = 0; f < 18; f++) sm[wp][f] = acc[f];
    }
    __syncthreads();
    if (tid < 18) {
        float t = 0.f;
        for (int k = 0; k < 8; k++) t += sm[k][tid];
        g_ppart[bid * 18 + tid] = t;
    }
}

// ---------------- pool phase B: finish pool + dueling head (64 threads) ----------------
__global__ void k_poolB(const int* __restrict__ cur, const int* __restrict__ mask,
                        const float* __restrict__ goal,
                        const float* __restrict__ Wv1, const float* __restrict__ bv1,
                        const float* __restrict__ Wv2, const float* __restrict__ bv2,
                        const float* __restrict__ Wa1, const float* __restrict__ ba1,
                        const float* __restrict__ Wa2, const float* __restrict__ ba2,
                        float* __restrict__ out) {
    int b = threadIdx.x;
    if (b >= NB) return;
    int n = b * NPER + cur[b];
    float feat[42];
#pragma unroll
    for (int j = 0; j < 5; j++) feat[j] = g_h2[n * 5 + j];
#pragma unroll
    for (int j = 0; j < 5; j++) feat[5 + j] = g_h1[n * 5 + j];
#pragma unroll
    for (int f = 0; f < 8; f++) feat[10 + f] = g_xn[n * 8 + f];
#pragma unroll
    for (int k = 0; k < 18; k++) {
        float t = 0.f;
        for (int c = 0; c < 8; c++) t += g_ppart[(b * 8 + c) * 18 + k];
        feat[18 + k] = t * (1.f / (float)NPER);
    }
#pragma unroll
    for (int k = 0; k < 6; k++) feat[36 + k] = goal[b * 6 + k];

    float hv[10], ha[10];
#pragma unroll
    for (int j = 0; j < 10; j++) { hv[j] = bv1[j]; ha[j] = ba1[j]; }
    for (int i = 0; i < 42; i++) {
        float fi = feat[i];
#pragma unroll
        for (int j = 0; j < 10; j++) {
            hv[j] = fmaf(fi, Wv1[i * 10 + j], hv[j]);
            ha[j] = fmaf(fi, Wa1[i * 10 + j], ha[j]);
        }
    }
#pragma unroll
    for (int j = 0; j < 10; j++) {
        hv[j] = (hv[j] > 0.f) ? hv[j] : 0.f;
        ha[j] = (ha[j] > 0.f) ? ha[j] : 0.f;
    }
    float val = bv2[0];
#pragma unroll
    for (int j = 0; j < 10; j++) val = fmaf(hv[j], Wv2[j], val);
    float adv[4];
#pragma unroll
    for (int k = 0; k < 4; k++) {
        adv[k] = ba2[k];
#pragma unroll
        for (int j = 0; j < 10; j++) adv[k] = fmaf(ha[j], Wa2[j * 4 + k], adv[k]);
    }
    float am = (adv[0] + adv[1] + adv[2] + adv[3]) * 0.25f;
#pragma unroll
    for (int k = 0; k < 4; k++)
        out[b * 4 + k] = (mask[b * 4 + k] == 0) ? -1e8f : (val + adv[k] - am);
}

// ---------------- launch ----------------
extern "C" void kernel_launch(void* const* d_in, const int* in_sizes, int n_in,
                              void* d_out, int out_size) {
    const float* x    = (const float*)d_in[0];
    const int*   ei   = (const int*)d_in[1];
    const float* ea   = (const float*)d_in[2];
    const int*   cur  = (const int*)d_in[4];
    const int*   mask = (const int*)d_in[5];
    const float* goal = (const float*)d_in[6];
    const float* gnw  = (const float*)d_in[7];
    const float* gnb  = (const float*)d_in[8];
    const float* gnms = (const float*)d_in[9];
    const float* Wl1 = (const float*)d_in[10], *bl1 = (const float*)d_in[11];
    const float* Wr1 = (const float*)d_in[12], *br1 = (const float*)d_in[13];
    const float* We1 = (const float*)d_in[14], *att1 = (const float*)d_in[15], *bo1 = (const float*)d_in[16];
    const float* Wl2 = (const float*)d_in[17], *bl2 = (const float*)d_in[18];
    const float* Wr2 = (const float*)d_in[19], *br2 = (const float*)d_in[20];
    const float* We2 = (const float*)d_in[21], *att2 = (const float*)d_in[22], *bo2 = (const float*)d_in[23];
    const float* Wv1 = (const float*)d_in[24], *bv1 = (const float*)d_in[25];
    const float* Wv2 = (const float*)d_in[26], *bv2 = (const float*)d_in[27];
    const float* Wa1 = (const float*)d_in[28], *ba1 = (const float*)d_in[29];
    const float* Wa2 = (const float*)d_in[30], *ba2 = (const float*)d_in[31];

    const int* srcp = ei;
    const int* dstp = ei + NE;

    const int EDGE_SMEM = NPER * 8 * 2;   // 128 KB fp8 tables
    cudaFuncSetAttribute(k_edgeB, cudaFuncAttributeMaxDynamicSharedMemorySize, EDGE_SMEM);
    cudaFuncSetAttribute(k_scatter4, cudaFuncAttributeMaxDynamicSharedMemorySize, SC_SMEM);

    k_gnA<<<512, 256>>>(x);                                             // 1
    k_gnB<<<2048, 256>>>(x, gnw, gnb, gnms, Wl1, bl1, Wr1, br1);        // 2
    k_scatter4<<<NTILE, TPB, SC_SMEM>>>(srcp, dstp, ea);                // 3
    k_edgeB<<<NB * NSLICE, 1024, EDGE_SMEM>>>(We1, att1);               // 4 <- ncu slot
    k_node1<<<NN / 256, 256>>>(We1, att1, bo1, Wl2, bl2, Wr2, br2);    // 5
    k_edgeB<<<NB * NSLICE, 1024, EDGE_SMEM>>>(We2, att2);               // 6
    k_node2poolA<<<512, 256>>>(We2, att2, bo2);                         // 7
    k_poolB<<<1, 64>>>(cur, mask, goal, Wv1, bv1, Wv2, bv2,
                       Wa1, ba1, Wa2, ba2, (float*)d_out);              // 8
}